// round 1
// baseline (speedup 1.0000x reference)
#include <cuda_runtime.h>

#define HH 512
#define WW 512
#define NCHUNK 8
#define RPC (HH / NCHUNK)   // 64 rows per warp-chunk

__device__ __forceinline__ int rrow(int r) {
    // reflect pad=1: -1 -> 1, 512 -> 510 (general reflect for safety)
    return r < 0 ? -r : (r >= HH ? 2 * HH - 2 - r : r);
}

__device__ __forceinline__ void sort3(float& a, float& b, float& c) {
    float t;
    t = fminf(a, b); b = fmaxf(a, b); a = t;
    t = fminf(b, c); c = fmaxf(b, c); b = t;
    t = fminf(a, b); b = fmaxf(a, b); a = t;
}

__device__ __forceinline__ float med3(float a, float b, float c) {
    return fmaxf(fminf(a, b), fminf(fmaxf(a, b), c));
}
__device__ __forceinline__ float max3(float a, float b, float c) { return fmaxf(fmaxf(a, b), c); }
__device__ __forceinline__ float min3(float a, float b, float c) { return fminf(fminf(a, b), c); }

// median of 9 given three sorted column triples (classic Smith network tail)
__device__ __forceinline__ float combine(
    float llo, float lmid, float lhi,
    float mlo, float mmid, float mhi,
    float rlo, float rmid, float rhi) {
    return med3(max3(llo, mlo, rlo), med3(lmid, mmid, rmid), min3(lhi, mhi, rhi));
}

__global__ __launch_bounds__(128, 8)
void median3x3_kernel(const float* __restrict__ x, float* __restrict__ out) {
    const int lane   = threadIdx.x & 31;
    const int stripe = threadIdx.x >> 5;   // 0..3, each warp owns 128 columns
    const int img    = blockIdx.y;         // 0..63
    const int chunk  = blockIdx.x;         // 0..7

    const float* __restrict__ base  = x   + (size_t)img * HH * WW;
    float* __restrict__       obase = out + (size_t)img * HH * WW;

    const int c0 = stripe * 128 + lane * 4;   // first of this lane's 4 columns
    const int y0 = chunk * RPC;
    const int y1 = y0 + RPC;

    // Edge lanes at interior stripe boundaries maintain one extra scalar column.
    const bool edge = (lane == 0 && stripe > 0) || (lane == 31 && stripe < 3);
    const int  xe   = (lane == 0) ? (c0 - 1) : (c0 + 4);

    // Prologue: rows y0-1, y0, y0+1 (row-reflected)
    float4 a4 = *(const float4*)(base + (size_t)rrow(y0 - 1) * WW + c0);
    float4 b4 = *(const float4*)(base + (size_t)y0 * WW + c0);
    float4 c4 = *(const float4*)(base + (size_t)rrow(y0 + 1) * WW + c0);
    float ae = 0.f, be = 0.f, ce = 0.f;
    if (edge) {
        ae = base[(size_t)rrow(y0 - 1) * WW + xe];
        be = base[(size_t)y0 * WW + xe];
        ce = base[(size_t)rrow(y0 + 1) * WW + xe];
    }

    for (int y = y0; y < y1; ++y) {
        // Sorted triples for the 4 owned columns (6 FMNMX each)
        float t0l = a4.x, t0m = b4.x, t0h = c4.x; sort3(t0l, t0m, t0h);
        float t1l = a4.y, t1m = b4.y, t1h = c4.y; sort3(t1l, t1m, t1h);
        float t2l = a4.z, t2m = b4.z, t2h = c4.z; sort3(t2l, t2m, t2h);
        float t3l = a4.w, t3m = b4.w, t3h = c4.w; sort3(t3l, t3m, t3h);
        // Edge column triple (only meaningful on edge lanes)
        float tel = ae, tem = be, teh = ce; sort3(tel, tem, teh);

        // Neighbor boundary triples via warp shuffle (6 SHFLs per 4 pixels)
        float Ll = __shfl_up_sync(0xffffffffu, t3l, 1);
        float Lm = __shfl_up_sync(0xffffffffu, t3m, 1);
        float Lh = __shfl_up_sync(0xffffffffu, t3h, 1);
        float Rl = __shfl_down_sync(0xffffffffu, t0l, 1);
        float Rm = __shfl_down_sync(0xffffffffu, t0m, 1);
        float Rh = __shfl_down_sync(0xffffffffu, t0h, 1);
        if (lane == 0) {
            if (stripe > 0) { Ll = tel; Lm = tem; Lh = teh; }
            else            { Ll = t1l; Lm = t1m; Lh = t1h; }   // reflect: col -1 -> col 1
        }
        if (lane == 31) {
            if (stripe < 3) { Rl = tel; Rm = tem; Rh = teh; }
            else            { Rl = t2l; Rm = t2m; Rh = t2h; }   // reflect: col 512 -> col 510
        }

        float4 o;
        o.x = combine(Ll,  Lm,  Lh,  t0l, t0m, t0h, t1l, t1m, t1h);
        o.y = combine(t0l, t0m, t0h, t1l, t1m, t1h, t2l, t2m, t2h);
        o.z = combine(t1l, t1m, t1h, t2l, t2m, t2h, t3l, t3m, t3h);
        o.w = combine(t2l, t2m, t2h, t3l, t3m, t3h, Rl,  Rm,  Rh);
        *(float4*)(obase + (size_t)y * WW + c0) = o;

        // Slide the 3-row window down by one
        a4 = b4; b4 = c4;
        const int yn = rrow(y + 2);
        c4 = *(const float4*)(base + (size_t)yn * WW + c0);
        ae = be; be = ce;
        if (edge) ce = base[(size_t)yn * WW + xe];
    }
}

extern "C" void kernel_launch(void* const* d_in, const int* in_sizes, int n_in,
                              void* d_out, int out_size) {
    const float* x = (const float*)d_in[0];
    float* out = (float*)d_out;
    const int nimg = in_sizes[0] / (HH * WW);   // 64 for [8,8,512,512]
    dim3 grid(NCHUNK, nimg);
    median3x3_kernel<<<grid, 128>>>(x, out);
}

// round 2
// speedup vs baseline: 1.3870x; 1.3870x over previous
#include <cuda_runtime.h>

#define HH 512
#define WW 512
#define NCHUNK 32
#define RPC (HH / NCHUNK)   // 16 rows per warp-chunk

__device__ __forceinline__ int rrow(int r) {
    // reflect pad=1: -1 -> 1, 512 -> 510
    return r < 0 ? -r : (r >= HH ? 2 * HH - 2 - r : r);
}

__device__ __forceinline__ void sort3(float& a, float& b, float& c) {
    float t;
    t = fminf(a, b); b = fmaxf(a, b); a = t;
    t = fminf(b, c); c = fmaxf(b, c); b = t;
    t = fminf(a, b); b = fmaxf(a, b); a = t;
}

__device__ __forceinline__ float med3(float a, float b, float c) {
    return fmaxf(fminf(a, b), fminf(fmaxf(a, b), c));
}
__device__ __forceinline__ float max3(float a, float b, float c) { return fmaxf(fmaxf(a, b), c); }
__device__ __forceinline__ float min3(float a, float b, float c) { return fminf(fminf(a, b), c); }

// median of 9 given three sorted column triples
__device__ __forceinline__ float combine(
    float llo, float lmid, float lhi,
    float mlo, float mmid, float mhi,
    float rlo, float rmid, float rhi) {
    return med3(max3(llo, mlo, rlo), med3(lmid, mmid, rmid), min3(lhi, mhi, rhi));
}

__global__ __launch_bounds__(128)
void median3x3_kernel(const float* __restrict__ x, float* __restrict__ out) {
    const int lane   = threadIdx.x & 31;
    const int stripe = threadIdx.x >> 5;   // 0..3, each warp owns 128 columns
    const int img    = blockIdx.y;         // 0..63
    const int chunk  = blockIdx.x;         // 0..NCHUNK-1

    const float* __restrict__ base  = x   + (size_t)img * HH * WW;
    float* __restrict__       obase = out + (size_t)img * HH * WW;

    const int c0 = stripe * 128 + lane * 4;   // first of this lane's 4 columns
    const int y0 = chunk * RPC;
    const int y1 = y0 + RPC;

    // Edge lanes at interior stripe boundaries maintain one extra scalar column.
    const bool edge = (lane == 0 && stripe > 0) || (lane == 31 && stripe < 3);
    const int  xe   = (lane == 0) ? (c0 - 1) : (c0 + 4);

    // Prologue: rows y0-1, y0, y0+1 (row-reflected)
    float4 a4 = __ldg((const float4*)(base + (size_t)rrow(y0 - 1) * WW + c0));
    float4 b4 = __ldg((const float4*)(base + (size_t)y0 * WW + c0));
    float4 c4 = __ldg((const float4*)(base + (size_t)rrow(y0 + 1) * WW + c0));
    float ae = 0.f, be = 0.f, ce = 0.f;
    if (edge) {
        ae = __ldg(base + (size_t)rrow(y0 - 1) * WW + xe);
        be = __ldg(base + (size_t)y0 * WW + xe);
        ce = __ldg(base + (size_t)rrow(y0 + 1) * WW + xe);
    }

    for (int y = y0; y < y1; ++y) {
        // Sorted triples for the 4 owned columns (6 FMNMX each)
        float t0l = a4.x, t0m = b4.x, t0h = c4.x; sort3(t0l, t0m, t0h);
        float t1l = a4.y, t1m = b4.y, t1h = c4.y; sort3(t1l, t1m, t1h);
        float t2l = a4.z, t2m = b4.z, t2h = c4.z; sort3(t2l, t2m, t2h);
        float t3l = a4.w, t3m = b4.w, t3h = c4.w; sort3(t3l, t3m, t3h);
        // Edge column triple (only meaningful on edge lanes)
        float tel = ae, tem = be, teh = ce; sort3(tel, tem, teh);

        // Neighbor boundary triples via warp shuffle
        float Ll = __shfl_up_sync(0xffffffffu, t3l, 1);
        float Lm = __shfl_up_sync(0xffffffffu, t3m, 1);
        float Lh = __shfl_up_sync(0xffffffffu, t3h, 1);
        float Rl = __shfl_down_sync(0xffffffffu, t0l, 1);
        float Rm = __shfl_down_sync(0xffffffffu, t0m, 1);
        float Rh = __shfl_down_sync(0xffffffffu, t0h, 1);
        if (lane == 0) {
            if (stripe > 0) { Ll = tel; Lm = tem; Lh = teh; }
            else            { Ll = t1l; Lm = t1m; Lh = t1h; }   // reflect col -1 -> 1
        }
        if (lane == 31) {
            if (stripe < 3) { Rl = tel; Rm = tem; Rh = teh; }
            else            { Rl = t2l; Rm = t2m; Rh = t2h; }   // reflect col 512 -> 510
        }

        float4 o;
        o.x = combine(Ll,  Lm,  Lh,  t0l, t0m, t0h, t1l, t1m, t1h);
        o.y = combine(t0l, t0m, t0h, t1l, t1m, t1h, t2l, t2m, t2h);
        o.z = combine(t1l, t1m, t1h, t2l, t2m, t2h, t3l, t3m, t3h);
        o.w = combine(t2l, t2m, t2h, t3l, t3m, t3h, Rl,  Rm,  Rh);
        *(float4*)(obase + (size_t)y * WW + c0) = o;

        // Slide the 3-row window down by one
        a4 = b4; b4 = c4;
        const int yn = rrow(y + 2);
        c4 = __ldg((const float4*)(base + (size_t)yn * WW + c0));
        ae = be; be = ce;
        if (edge) ce = __ldg(base + (size_t)yn * WW + xe);
    }
}

extern "C" void kernel_launch(void* const* d_in, const int* in_sizes, int n_in,
                              void* d_out, int out_size) {
    const float* x = (const float*)d_in[0];
    float* out = (float*)d_out;
    const int nimg = in_sizes[0] / (HH * WW);   // 64 for [8,8,512,512]
    dim3 grid(NCHUNK, nimg);
    median3x3_kernel<<<grid, 128>>>(x, out);
}

// round 3
// speedup vs baseline: 1.6870x; 1.2163x over previous
#include <cuda_runtime.h>

#define HH 512
#define WW 512
#define NCHUNK 32
#define RPC (HH / NCHUNK)   // 16 rows per block

__device__ __forceinline__ int rrow(int r) {
    // reflect pad=1 (general reflect for prefetch safety)
    return r < 0 ? -r : (r >= HH ? 2 * HH - 2 - r : r);
}

__device__ __forceinline__ float med3(float a, float b, float c) {
    return fmaxf(fminf(a, b), fminf(fmaxf(a, b), c));
}
__device__ __forceinline__ float max3(float a, float b, float c) { return fmaxf(fmaxf(a, b), c); }
__device__ __forceinline__ float min3(float a, float b, float c) { return fminf(fminf(a, b), c); }

// median of 9 given three sorted column triples
__device__ __forceinline__ float combine(
    float llo, float lmid, float lhi,
    float mlo, float mmid, float mhi,
    float rlo, float rmid, float rhi) {
    return med3(max3(llo, mlo, rlo), med3(lmid, mmid, rmid), min3(lhi, mhi, rhi));
}

// insert a into sorted pair (p <= q) -> sorted triple (4 ops)
__device__ __forceinline__ void ins3(float a, float p, float q,
                                     float& lo, float& mi, float& hi) {
    lo = fminf(a, p);
    hi = fmaxf(a, q);
    mi = fmaxf(p, fminf(a, q));
}

// one output row: shuffles + boundary fixups + 4 combines + store
__device__ __forceinline__ void emit_row(
    const float tl0, const float tm0, const float th0,
    const float tl1, const float tm1, const float th1,
    const float tl2, const float tm2, const float th2,
    const float tl3, const float tm3, const float th3,
    const float tel, const float tem, const float teh,
    int lane, int stripe, float* __restrict__ orow) {

    float Ll = __shfl_up_sync(0xffffffffu, tl3, 1);
    float Lm = __shfl_up_sync(0xffffffffu, tm3, 1);
    float Lh = __shfl_up_sync(0xffffffffu, th3, 1);
    float Rl = __shfl_down_sync(0xffffffffu, tl0, 1);
    float Rm = __shfl_down_sync(0xffffffffu, tm0, 1);
    float Rh = __shfl_down_sync(0xffffffffu, th0, 1);
    if (lane == 0) {
        if (stripe > 0) { Ll = tel; Lm = tem; Lh = teh; }
        else            { Ll = tl1; Lm = tm1; Lh = th1; }   // reflect col -1 -> 1
    }
    if (lane == 31) {
        if (stripe < 3) { Rl = tel; Rm = tem; Rh = teh; }
        else            { Rl = tl2; Rm = tm2; Rh = th2; }   // reflect col 512 -> 510
    }

    float4 o;
    o.x = combine(Ll,  Lm,  Lh,  tl0, tm0, th0, tl1, tm1, th1);
    o.y = combine(tl0, tm0, th0, tl1, tm1, th1, tl2, tm2, th2);
    o.z = combine(tl1, tm1, th1, tl2, tm2, th2, tl3, tm3, th3);
    o.w = combine(tl2, tm2, th2, tl3, tm3, th3, Rl,  Rm,  Rh);
    *(float4*)orow = o;
}

__global__ __launch_bounds__(128, 9)
void median3x3_kernel(const float* __restrict__ x, float* __restrict__ out) {
    const int lane   = threadIdx.x & 31;
    const int stripe = threadIdx.x >> 5;   // 0..3, each warp owns 128 columns
    const int img    = blockIdx.y;
    const int chunk  = blockIdx.x;

    const float* __restrict__ base  = x   + (size_t)img * HH * WW;
    float* __restrict__       obase = out + (size_t)img * HH * WW;

    const int c0 = stripe * 128 + lane * 4;
    const int y0 = chunk * RPC;

    // Interior-stripe boundary lanes maintain one extra scalar column.
    const bool edge = (lane == 0 && stripe > 0) || (lane == 31 && stripe < 3);
    const int  xe   = (lane == 0) ? (c0 - 1) : (c0 + 4);

    // Rolling window rows: a=y-1, b=y, c=y+1 (d,n loaded in-loop)
    float4 a4 = __ldg((const float4*)(base + (size_t)rrow(y0 - 1) * WW + c0));
    float4 b4 = __ldg((const float4*)(base + (size_t)y0 * WW + c0));
    float4 c4 = __ldg((const float4*)(base + (size_t)(y0 + 1) * WW + c0));
    float ae = 0.f, be = 0.f, ce = 0.f;
    if (edge) {
        ae = __ldg(base + (size_t)rrow(y0 - 1) * WW + xe);
        be = __ldg(base + (size_t)y0 * WW + xe);
        ce = __ldg(base + (size_t)(y0 + 1) * WW + xe);
    }

#pragma unroll 2
    for (int y = y0; y < y0 + RPC; y += 2) {
        // Prefetch rows y+2 and y+3 at loop top (2 independent LDGs in flight)
        const int y2 = rrow(y + 2);
        const int y3 = rrow(y + 3);
        float4 d4 = __ldg((const float4*)(base + (size_t)y2 * WW + c0));
        float4 n4 = __ldg((const float4*)(base + (size_t)y3 * WW + c0));
        float de = 0.f, ne = 0.f;
        if (edge) {
            de = __ldg(base + (size_t)y2 * WW + xe);
            ne = __ldg(base + (size_t)y3 * WW + xe);
        }

        // Sorted pair of the two shared rows (b=y, c=y+1), per column
        float p0 = fminf(b4.x, c4.x), q0 = fmaxf(b4.x, c4.x);
        float p1 = fminf(b4.y, c4.y), q1 = fmaxf(b4.y, c4.y);
        float p2 = fminf(b4.z, c4.z), q2 = fmaxf(b4.z, c4.z);
        float p3 = fminf(b4.w, c4.w), q3 = fmaxf(b4.w, c4.w);
        float pe = fminf(be, ce),     qe = fmaxf(be, ce);

        // ---- output row y: insert row y-1 (a) ----
        {
            float l0,m0,h0,l1,m1,h1,l2,m2,h2,l3,m3,h3,le,me,he;
            ins3(a4.x, p0, q0, l0, m0, h0);
            ins3(a4.y, p1, q1, l1, m1, h1);
            ins3(a4.z, p2, q2, l2, m2, h2);
            ins3(a4.w, p3, q3, l3, m3, h3);
            ins3(ae,   pe, qe, le, me, he);
            emit_row(l0,m0,h0, l1,m1,h1, l2,m2,h2, l3,m3,h3, le,me,he,
                     lane, stripe, obase + (size_t)y * WW + c0);
        }

        // ---- output row y+1: insert row y+2 (d) ----
        {
            float l0,m0,h0,l1,m1,h1,l2,m2,h2,l3,m3,h3,le,me,he;
            ins3(d4.x, p0, q0, l0, m0, h0);
            ins3(d4.y, p1, q1, l1, m1, h1);
            ins3(d4.z, p2, q2, l2, m2, h2);
            ins3(d4.w, p3, q3, l3, m3, h3);
            ins3(de,   pe, qe, le, me, he);
            emit_row(l0,m0,h0, l1,m1,h1, l2,m2,h2, l3,m3,h3, le,me,he,
                     lane, stripe, obase + (size_t)(y + 1) * WW + c0);
        }

        // slide window down by 2
        a4 = c4; b4 = d4; c4 = n4;
        ae = ce; be = de; ce = ne;
    }
}

extern "C" void kernel_launch(void* const* d_in, const int* in_sizes, int n_in,
                              void* d_out, int out_size) {
    const float* x = (const float*)d_in[0];
    float* out = (float*)d_out;
    const int nimg = in_sizes[0] / (HH * WW);   // 64 for [8,8,512,512]
    dim3 grid(NCHUNK, nimg);
    median3x3_kernel<<<grid, 128>>>(x, out);
}